// round 1
// baseline (speedup 1.0000x reference)
#include <cuda_runtime.h>
#include <cstdint>

#define HH   64
#define WW   128
#define CINC 128
#define COUTC 128
#define NIMG 16    // B(4) * 4 feature groups

// Scratch (static __device__ arrays: allocation-free per harness rules)
__device__ float g_xr[NIMG * CINC * HH * WW];      // BN+ReLU'd input, NCHW (67 MB)
__device__ float g_feat[NIMG * HH * WW * COUTC];   // normalized conv features, channel-last (67 MB)
__device__ float g_wt[CINC * 9 * COUTC];           // weights re-laid-out [ci][k][co]

typedef unsigned long long ull;

__device__ __forceinline__ void ffma2(ull& acc, ull a, ull b) {
    asm("fma.rn.f32x2 %0, %1, %2, %0;" : "+l"(acc) : "l"(a), "l"(b));
}
__device__ __forceinline__ ull pack2(float v) {
    ull r; unsigned u = __float_as_uint(v);
    asm("mov.b64 %0, {%1, %1};" : "=l"(r) : "r"(u));
    return r;
}
__device__ __forceinline__ float2 unpack2(ull a) {
    float2 v;
    v.x = __uint_as_float((unsigned)(a & 0xffffffffULL));
    v.y = __uint_as_float((unsigned)(a >> 32));
    return v;
}

// ---------------------------------------------------------------------------
// Kernel 1: BN + ReLU elementwise (x -> g_xr), float4 grid-stride
// ---------------------------------------------------------------------------
__global__ void bn_relu_kernel(const float* __restrict__ x,
                               const float* __restrict__ gamma,
                               const float* __restrict__ beta,
                               const float* __restrict__ mean,
                               const float* __restrict__ var) {
    const int total4 = NIMG * CINC * HH * WW / 4;
    for (int i = blockIdx.x * blockDim.x + threadIdx.x; i < total4;
         i += gridDim.x * blockDim.x) {
        int ci = (i >> 11) & 127;  // (4*i / 8192) % 128
        float s  = gamma[ci] * rsqrtf(var[ci] + 1e-5f);
        float sh = beta[ci] - mean[ci] * s;
        float4 v = ((const float4*)x)[i];
        v.x = fmaxf(fmaf(v.x, s, sh), 0.f);
        v.y = fmaxf(fmaf(v.y, s, sh), 0.f);
        v.z = fmaxf(fmaf(v.z, s, sh), 0.f);
        v.w = fmaxf(fmaf(v.w, s, sh), 0.f);
        ((float4*)g_xr)[i] = v;
    }
}

// ---------------------------------------------------------------------------
// Kernel 2: weight relayout (OIHW -> [ci][ky*3+kx][co]) for coalesced smem fill
// ---------------------------------------------------------------------------
__global__ void wtrans_kernel(const float* __restrict__ cw) {
    int i = blockIdx.x * blockDim.x + threadIdx.x;
    if (i < CINC * 9 * COUTC) {
        int co = i & 127;
        int k  = (i >> 7) % 9;
        int ci = i / (128 * 9);
        g_wt[i] = cw[(co * CINC + ci) * 9 + k];
    }
}

// ---------------------------------------------------------------------------
// Kernel 3: 3x3 conv (pad 1) + fused channel L2-normalize.
// Block = one (image n, output row h): all 128 couts x 128 w.
// 256 threads: tx = tid&15 owns 8 w, cy = tid>>4 owns 8 couts (as 4 f32x2 pairs).
// K-chunks of 4 input channels staged in smem; FFMA2 packed over cout pairs.
// Writes normalized features channel-last to g_feat.
// ---------------------------------------------------------------------------
#define CK 4
struct SmemA { float in_s[CK][3][130]; float w_s[CK][9][COUTC]; };
struct SmemB { float red[16][WW]; float invs[WW]; };
union ConvSmem { SmemA a; SmemB b; };

__global__ void __launch_bounds__(256, 2) conv_norm_kernel() {
    __shared__ __align__(16) ConvSmem sm;

    const int h = blockIdx.x;
    const int n = blockIdx.y;
    const int tid = threadIdx.x;
    const int tx = tid & 15;    // w group: w = tx*8 + jw
    const int cy = tid >> 4;    // cout group: co = cy*8 + 2*cop + {0,1}

    ull acc[4][8];
#pragma unroll
    for (int c = 0; c < 4; c++)
#pragma unroll
        for (int j = 0; j < 8; j++) acc[c][j] = 0ULL;

    const float* xbase = g_xr + n * CINC * HH * WW;

    for (int cc = 0; cc < CINC / CK; cc++) {
        const int ci0 = cc * CK;
        // stage input: CK ci x 3 rows x 130 w (with zero halo)
        for (int i = tid; i < CK * 3 * 130; i += 256) {
            int ci  = i / 390;
            int rem = i - ci * 390;
            int r   = rem / 130;
            int wi  = rem - r * 130;
            int hr  = h + r - 1;
            int gw  = wi - 1;
            float v = 0.f;
            if (hr >= 0 && hr < HH && gw >= 0 && gw < WW)
                v = xbase[(ci0 + ci) * (HH * WW) + hr * WW + gw];
            sm.a.in_s[ci][r][wi] = v;
        }
        // stage weights: contiguous copy thanks to g_wt layout
        {
            const float4* src = (const float4*)(g_wt + ci0 * 9 * COUTC);
            float4* dst = (float4*)sm.a.w_s;
            for (int i = tid; i < CK * 9 * COUTC / 4; i += 256) dst[i] = src[i];
        }
        __syncthreads();

#pragma unroll
        for (int ci = 0; ci < CK; ci++) {
#pragma unroll
            for (int ky = 0; ky < 3; ky++) {
                ull a2[10];
                const float* ib = &sm.a.in_s[ci][ky][tx * 8];
#pragma unroll
                for (int j = 0; j < 10; j++) a2[j] = pack2(ib[j]);
#pragma unroll
                for (int kx = 0; kx < 3; kx++) {
                    const ull* wp = (const ull*)&sm.a.w_s[ci][ky * 3 + kx][cy * 8];
                    ull b0 = wp[0], b1 = wp[1], b2 = wp[2], b3 = wp[3];
#pragma unroll
                    for (int jw = 0; jw < 8; jw++) {
                        ffma2(acc[0][jw], b0, a2[jw + kx]);
                        ffma2(acc[1][jw], b1, a2[jw + kx]);
                        ffma2(acc[2][jw], b2, a2[jw + kx]);
                        ffma2(acc[3][jw], b3, a2[jw + kx]);
                    }
                }
            }
        }
        __syncthreads();
    }

    // ---- fused L2 normalization over couts (per pixel) ----
#pragma unroll
    for (int jw = 0; jw < 8; jw++) {
        float s = 0.f;
#pragma unroll
        for (int c = 0; c < 4; c++) {
            float2 v = unpack2(acc[c][jw]);
            s += v.x * v.x + v.y * v.y;
        }
        sm.b.red[cy][tx * 8 + jw] = s;
    }
    __syncthreads();
    if (tid < WW) {
        float s = 0.f;
#pragma unroll
        for (int g = 0; g < 16; g++) s += sm.b.red[g][tid];
        sm.b.invs[tid] = rsqrtf(s);
    }
    __syncthreads();

    float* ob = g_feat + ((n * HH + h) * WW) * COUTC;
#pragma unroll
    for (int jw = 0; jw < 8; jw++) {
        int w = tx * 8 + jw;
        float iv = sm.b.invs[w];
        float2 v0 = unpack2(acc[0][jw]);
        float2 v1 = unpack2(acc[1][jw]);
        float2 v2 = unpack2(acc[2][jw]);
        float2 v3 = unpack2(acc[3][jw]);
        float4 o0 = make_float4(v0.x * iv, v0.y * iv, v1.x * iv, v1.y * iv);
        float4 o1 = make_float4(v2.x * iv, v2.y * iv, v3.x * iv, v3.y * iv);
        float4* dst = (float4*)(ob + w * COUTC + cy * 8);
        dst[0] = o0;
        dst[1] = o1;
    }
}

// ---------------------------------------------------------------------------
// Kernel 4: 9x9 dilated (x2) correlation on channel-last normalized features.
// Block = (pair, b, h); 128 threads = full W row; each thread keeps all 81
// accumulators in registers; channels chunked by 16 with f1 chunk cached in
// registers; f2 row chunk staged in XOR-swizzled smem (conflict-free LDS.128).
// ---------------------------------------------------------------------------
__global__ void corr_kernel(float* __restrict__ out) {
    const int h = blockIdx.x;
    const int pair = blockIdx.y % 3;
    const int b = blockIdx.y / 3;
    const int n1 = b * 4 + pair;
    const int n2 = n1 + 1;
    const int w = threadIdx.x;  // 0..127

    __shared__ __align__(16) float4 f2s[144][4];  // w2 in [-8,135]+8, 16 channels

    float acc[81];
#pragma unroll
    for (int p = 0; p < 81; p++) acc[p] = 0.f;

    const float4* f1p = (const float4*)(g_feat) + ((size_t)(n1 * HH + h) * WW + w) * (COUTC / 4);

    for (int ch = 0; ch < 8; ch++) {  // 8 chunks of 16 channels
        float4 A0 = f1p[ch * 4 + 0];
        float4 A1 = f1p[ch * 4 + 1];
        float4 A2 = f1p[ch * 4 + 2];
        float4 A3 = f1p[ch * 4 + 3];
#pragma unroll
        for (int py = 0; py < 9; py++) {
            int row = h + py * 2 - 8;
            bool rok = (row >= 0) && (row < HH);
            __syncthreads();
            {
                const float4* f2base = (const float4*)(g_feat) + (size_t)(n2 * HH + (rok ? row : 0)) * WW * (COUTC / 4);
                for (int i = threadIdx.x; i < 144 * 4; i += 128) {
                    int w2 = i >> 2;
                    int c4 = i & 3;
                    int gw = w2 - 8;
                    float4 v = make_float4(0.f, 0.f, 0.f, 0.f);
                    if (rok && gw >= 0 && gw < WW)
                        v = f2base[gw * (COUTC / 4) + ch * 4 + c4];
                    f2s[w2][c4 ^ ((w2 >> 3) & 3)] = v;
                }
            }
            __syncthreads();
#pragma unroll
            for (int px = 0; px < 9; px++) {
                int w2 = w + px * 2;
                int sw = (w2 >> 3) & 3;
                float s = acc[py * 9 + px];
                {
                    float4 Bv = f2s[w2][0 ^ sw];
                    s += A0.x * Bv.x + A0.y * Bv.y + A0.z * Bv.z + A0.w * Bv.w;
                }
                {
                    float4 Bv = f2s[w2][1 ^ sw];
                    s += A1.x * Bv.x + A1.y * Bv.y + A1.z * Bv.z + A1.w * Bv.w;
                }
                {
                    float4 Bv = f2s[w2][2 ^ sw];
                    s += A2.x * Bv.x + A2.y * Bv.y + A2.z * Bv.z + A2.w * Bv.w;
                }
                {
                    float4 Bv = f2s[w2][3 ^ sw];
                    s += A3.x * Bv.x + A3.y * Bv.y + A3.z * Bv.z + A3.w * Bv.w;
                }
                acc[py * 9 + px] = s;
            }
        }
    }

    float* ob = out + ((size_t)(b * 243 + pair * 81) * HH + h) * WW + w;
#pragma unroll
    for (int p = 0; p < 81; p++) ob[(size_t)p * HH * WW] = acc[p];
}

// ---------------------------------------------------------------------------
extern "C" void kernel_launch(void* const* d_in, const int* in_sizes, int n_in,
                              void* d_out, int out_size) {
    const float* x     = (const float*)d_in[0];
    const float* gamma = (const float*)d_in[1];
    const float* beta  = (const float*)d_in[2];
    const float* mean  = (const float*)d_in[3];
    const float* var   = (const float*)d_in[4];
    const float* cw    = (const float*)d_in[5];
    float* out = (float*)d_out;

    bn_relu_kernel<<<2048, 256>>>(x, gamma, beta, mean, var);
    wtrans_kernel<<<(CINC * 9 * COUTC + 255) / 256, 256>>>(cw);
    conv_norm_kernel<<<dim3(HH, NIMG), 256>>>();
    corr_kernel<<<dim3(HH, 12), 128>>>(out);
}

// round 6
// speedup vs baseline: 1.1965x; 1.1965x over previous
#include <cuda_runtime.h>
#include <cstdint>

#define HH   64
#define WW   128
#define CINC 128
#define COUTC 128
#define NIMG 16    // B(4) * 4 feature groups

// Scratch (static __device__ arrays: allocation-free per harness rules)
__device__ float g_feat[NIMG * HH * WW * COUTC];   // normalized conv features, channel-last (67 MB)
__device__ float g_wt[CINC * 9 * COUTC];           // weights re-laid-out [ci][k][co]
__device__ float g_bns[CINC];                      // BN scale  = gamma*rsqrt(var+eps)
__device__ float g_bnb[CINC];                      // BN shift  = beta - mean*scale

typedef unsigned long long ull;

__device__ __forceinline__ void ffma2(ull& acc, ull a, ull b) {
    asm("fma.rn.f32x2 %0, %1, %2, %0;" : "+l"(acc) : "l"(a), "l"(b));
}
__device__ __forceinline__ ull pack2(float v) {
    ull r; unsigned u = __float_as_uint(v);
    asm("mov.b64 %0, {%1, %1};" : "=l"(r) : "r"(u));
    return r;
}
__device__ __forceinline__ float2 unpack2(ull a) {
    float2 v;
    v.x = __uint_as_float((unsigned)(a & 0xffffffffULL));
    v.y = __uint_as_float((unsigned)(a >> 32));
    return v;
}

// ---------------------------------------------------------------------------
// Kernel 1: prep — weight relayout (OIHW -> [ci][k][co]) + BN scale/shift
// ---------------------------------------------------------------------------
__global__ void prep_kernel(const float* __restrict__ cw,
                            const float* __restrict__ gamma,
                            const float* __restrict__ beta,
                            const float* __restrict__ mean,
                            const float* __restrict__ var) {
    int i = blockIdx.x * blockDim.x + threadIdx.x;
    if (i < CINC) {
        float s = gamma[i] * rsqrtf(var[i] + 1e-5f);
        g_bns[i] = s;
        g_bnb[i] = beta[i] - mean[i] * s;
    }
    if (i < CINC * 9 * COUTC) {
        int co = i & 127;
        int k  = (i >> 7) % 9;
        int ci = i / (128 * 9);
        g_wt[i] = cw[(co * CINC + ci) * 9 + k];
    }
}

// ---------------------------------------------------------------------------
// Kernel 2: fused BN+ReLU + 3x3 conv (pad 1) + channel L2-normalize.
// Block = one (image n, output row h): all 128 couts x 128 w.
// 256 threads: tx = tid&15 owns 8 w, cy = tid>>4 owns 8 couts (4 f32x2 pairs).
// Input rows staged with bank swizzle w^( (w>>5)&3 ): the strided per-lane
// reads (stride 32B over 16 tx) become conflict-free.
// ---------------------------------------------------------------------------
#define CK 4
struct SmemA { float in_s[CK][3][132]; float w_s[CK][9][COUTC]; };
struct SmemB { float red[16][WW]; float invs[WW]; };
union ConvSmem { SmemA a; SmemB b; };

__device__ __forceinline__ int iswz(int w) { return w ^ ((w >> 5) & 3); }

__global__ void __launch_bounds__(256, 2) conv_norm_kernel(const float* __restrict__ x) {
    __shared__ __align__(16) ConvSmem sm;

    const int h = blockIdx.x;
    const int n = blockIdx.y;
    const int tid = threadIdx.x;
    const int tx = tid & 15;    // w group: w = tx*8 + jw
    const int cy = tid >> 4;    // cout group: co = cy*8 + 2*cop + {0,1}

    ull acc[4][8];
#pragma unroll
    for (int c = 0; c < 4; c++)
#pragma unroll
        for (int j = 0; j < 8; j++) acc[c][j] = 0ULL;

    const float* xbase = x + (size_t)n * CINC * HH * WW;

    for (int cc = 0; cc < CINC / CK; cc++) {
        const int ci0 = cc * CK;
        // stage input with fused BN+ReLU: CK ci x 3 rows x 130 w (zero halo)
        for (int i = tid; i < CK * 3 * 130; i += 256) {
            int ci  = i / 390;
            int rem = i - ci * 390;
            int r   = rem / 130;
            int wi  = rem - r * 130;
            int hr  = h + r - 1;
            int gw  = wi - 1;
            float v = 0.f;
            if (hr >= 0 && hr < HH && gw >= 0 && gw < WW) {
                float s  = g_bns[ci0 + ci];
                float sh = g_bnb[ci0 + ci];
                v = fmaxf(fmaf(xbase[(ci0 + ci) * (HH * WW) + hr * WW + gw], s, sh), 0.f);
            }
            sm.a.in_s[ci][r][iswz(wi)] = v;
        }
        // stage weights: contiguous copy thanks to g_wt layout
        {
            const float4* src = (const float4*)(g_wt + ci0 * 9 * COUTC);
            float4* dst = (float4*)sm.a.w_s;
            for (int i = tid; i < CK * 9 * COUTC / 4; i += 256) dst[i] = src[i];
        }
        __syncthreads();

#pragma unroll
        for (int ci = 0; ci < CK; ci++) {
#pragma unroll
            for (int ky = 0; ky < 3; ky++) {
                ull a2[10];
                const float* ib = &sm.a.in_s[ci][ky][0];
#pragma unroll
                for (int j = 0; j < 10; j++) a2[j] = pack2(ib[iswz(tx * 8 + j)]);
#pragma unroll
                for (int kx = 0; kx < 3; kx++) {
                    const ull* wp = (const ull*)&sm.a.w_s[ci][ky * 3 + kx][cy * 8];
                    ull b0 = wp[0], b1 = wp[1], b2 = wp[2], b3 = wp[3];
#pragma unroll
                    for (int jw = 0; jw < 8; jw++) {
                        ffma2(acc[0][jw], b0, a2[jw + kx]);
                        ffma2(acc[1][jw], b1, a2[jw + kx]);
                        ffma2(acc[2][jw], b2, a2[jw + kx]);
                        ffma2(acc[3][jw], b3, a2[jw + kx]);
                    }
                }
            }
        }
        __syncthreads();
    }

    // ---- fused L2 normalization over couts (per pixel) ----
#pragma unroll
    for (int jw = 0; jw < 8; jw++) {
        float s = 0.f;
#pragma unroll
        for (int c = 0; c < 4; c++) {
            float2 v = unpack2(acc[c][jw]);
            s += v.x * v.x + v.y * v.y;
        }
        sm.b.red[cy][tx * 8 + jw] = s;
    }
    __syncthreads();
    if (tid < WW) {
        float s = 0.f;
#pragma unroll
        for (int g = 0; g < 16; g++) s += sm.b.red[g][tid];
        sm.b.invs[tid] = rsqrtf(s);
    }
    __syncthreads();

    float* ob = g_feat + ((size_t)(n * HH + h) * WW) * COUTC;
#pragma unroll
    for (int jw = 0; jw < 8; jw++) {
        int w = tx * 8 + jw;
        float iv = sm.b.invs[w];
        float2 v0 = unpack2(acc[0][jw]);
        float2 v1 = unpack2(acc[1][jw]);
        float2 v2 = unpack2(acc[2][jw]);
        float2 v3 = unpack2(acc[3][jw]);
        float4 o0 = make_float4(v0.x * iv, v0.y * iv, v1.x * iv, v1.y * iv);
        float4 o1 = make_float4(v2.x * iv, v2.y * iv, v3.x * iv, v3.y * iv);
        float4* dst = (float4*)(ob + w * COUTC + cy * 8);
        dst[0] = o0;
        dst[1] = o1;
    }
}

// ---------------------------------------------------------------------------
// Kernel 3: 9x9 dilated (x2) correlation, v2.
// Warp = one task (pair, b, h, py). Thread owns 4 w positions spaced 2 apart
// (w = 8k + e + 2j, k=lane>>1, e=lane&1), so the 12 staged B columns
// [base, base+22] serve all 36 (px, j) accumulator updates -> 3x fewer LDS.
// Warp-private staging region with __syncwarp only; coset-XOR swizzle keeps
// the strided LDS.128 conflict-free.
// ---------------------------------------------------------------------------
__device__ __forceinline__ int cswz(int col, int c2) {
    int k = col >> 3;
    int g = ((k << 1) | (k & 1)) & 7;
    return (col * 2 + c2) ^ g;
}

__device__ __forceinline__ float dot8(const float4 a0, const float4 a1,
                                      const float4 b0, const float4 b1, float s) {
    s = fmaf(a0.x, b0.x, s); s = fmaf(a0.y, b0.y, s);
    s = fmaf(a0.z, b0.z, s); s = fmaf(a0.w, b0.w, s);
    s = fmaf(a1.x, b1.x, s); s = fmaf(a1.y, b1.y, s);
    s = fmaf(a1.z, b1.z, s); s = fmaf(a1.w, b1.w, s);
    return s;
}

__global__ void __launch_bounds__(256, 2) corr_kernel(float* __restrict__ out) {
    __shared__ __align__(16) float4 f2s[8][288];

    const int warp = threadIdx.x >> 5;
    const int lane = threadIdx.x & 31;
    int task = blockIdx.x * 8 + warp;           // 6912 tasks total
    int py  = task % 9;
    int rem = task / 9;
    int h   = rem & 63;
    int pb  = rem >> 6;                          // 0..11
    int pair = pb % 3, b = pb / 3;
    int n1 = b * 4 + pair, n2 = n1 + 1;
    int row = h + 2 * py - 8;

    const int base = ((lane >> 1) << 3) | (lane & 1);   // owned w = base + 2j
    float* ob = out + (size_t)(b * 243 + pair * 81 + py * 9) * (HH * WW) + h * WW;

    if (row < 0 || row >= HH) {
#pragma unroll
        for (int px = 0; px < 9; px++)
#pragma unroll
            for (int j = 0; j < 4; j++)
                ob[(size_t)px * (HH * WW) + base + 2 * j] = 0.f;
        return;
    }

    float acc[36];
#pragma unroll
    for (int i = 0; i < 36; i++) acc[i] = 0.f;

    const float4* f1p = (const float4*)g_feat + (size_t)(n1 * HH + h) * WW * (COUTC / 4);
    const float4* f2p = (const float4*)g_feat + (size_t)(n2 * HH + row) * WW * (COUTC / 4);

    for (int ch = 0; ch < 16; ch++) {            // 16 chunks of 8 channels
        __syncwarp();
        // warp-private stage: 144 cols x 2 float4 (8 channels), halo zero
#pragma unroll
        for (int m = 0; m < 9; m++) {
            int i = lane + 32 * m;
            int col = i >> 1, c2 = i & 1;
            int gw = col - 8;
            float4 v = make_float4(0.f, 0.f, 0.f, 0.f);
            if (gw >= 0 && gw < WW) v = f2p[gw * (COUTC / 4) + ch * 2 + c2];
            f2s[warp][cswz(col, c2)] = v;
        }
        __syncwarp();

        float4 A[4][2];
#pragma unroll
        for (int j = 0; j < 4; j++) {
            A[j][0] = f1p[(base + 2 * j) * (COUTC / 4) + ch * 2 + 0];
            A[j][1] = f1p[(base + 2 * j) * (COUTC / 4) + ch * 2 + 1];
        }

#pragma unroll
        for (int t = 0; t < 12; t++) {
            int col = base + 2 * t;
            float4 B0 = f2s[warp][cswz(col, 0)];
            float4 B1 = f2s[warp][cswz(col, 1)];
#pragma unroll
            for (int j = 0; j < 4; j++) {
                int px = t - j;
                if (px >= 0 && px < 9)
                    acc[px * 4 + j] = dot8(A[j][0], A[j][1], B0, B1, acc[px * 4 + j]);
            }
        }
    }

#pragma unroll
    for (int px = 0; px < 9; px++)
#pragma unroll
        for (int j = 0; j < 4; j++)
            ob[(size_t)px * (HH * WW) + base + 2 * j] = acc[px * 4 + j];
}

// ---------------------------------------------------------------------------
extern "C" void kernel_launch(void* const* d_in, const int* in_sizes, int n_in,
                              void* d_out, int out_size) {
    const float* x     = (const float*)d_in[0];
    const float* gamma = (const float*)d_in[1];
    const float* beta  = (const float*)d_in[2];
    const float* mean  = (const float*)d_in[3];
    const float* var   = (const float*)d_in[4];
    const float* cw    = (const float*)d_in[5];
    float* out = (float*)d_out;

    prep_kernel<<<(CINC * 9 * COUTC + 255) / 256, 256>>>(cw, gamma, beta, mean, var);
    conv_norm_kernel<<<dim3(HH, NIMG), 256>>>(x);
    corr_kernel<<<6912 / 8, 256>>>(out);
}

// round 15
// speedup vs baseline: 1.3735x; 1.1479x over previous
#include <cuda_runtime.h>
#include <cuda_bf16.h>
#include <cstdint>

#define HH   64
#define WW   128
#define NIMG 16
#define HP   66
#define WP   130

// ---------------- scratch (static device arrays; allocation-free) ----------
__device__ __nv_bfloat16 g_xh[(size_t)NIMG * HP * WP * 128];   // BN+ReLU input hi, channel-last, padded
__device__ __nv_bfloat16 g_xl[(size_t)NIMG * HP * WP * 128];   // lo part
__device__ __nv_bfloat16 g_wh[9 * 128 * 128];                  // weights hi  [k][co][ci]
__device__ __nv_bfloat16 g_wl[9 * 128 * 128];                  // weights lo
__device__ float g_feat[(size_t)NIMG * HH * WW * 128];         // normalized features, channel-last
__device__ float g_bns[128];
__device__ float g_bnb[128];

__device__ __forceinline__ uint32_t smem_to_u32(const void* p) {
    uint32_t a;
    asm("{ .reg .u64 t; cvta.to.shared.u64 t, %1; cvt.u32.u64 %0, t; }" : "=r"(a) : "l"(p));
    return a;
}
__device__ __forceinline__ void ldmatrix_x4(uint32_t* r, uint32_t addr) {
    asm volatile("ldmatrix.sync.aligned.m8n8.x4.shared.b16 {%0,%1,%2,%3}, [%4];"
                 : "=r"(r[0]), "=r"(r[1]), "=r"(r[2]), "=r"(r[3]) : "r"(addr));
}
__device__ __forceinline__ void mma_bf16(float4& d, const uint32_t* a, uint32_t b0, uint32_t b1) {
    asm volatile("mma.sync.aligned.m16n8k16.row.col.f32.bf16.bf16.f32 "
                 "{%0,%1,%2,%3}, {%4,%5,%6,%7}, {%8,%9}, {%0,%1,%2,%3};"
                 : "+f"(d.x), "+f"(d.y), "+f"(d.z), "+f"(d.w)
                 : "r"(a[0]), "r"(a[1]), "r"(a[2]), "r"(a[3]), "r"(b0), "r"(b1));
}

// ---------------------------------------------------------------------------
// zero-fill padded input arrays (padding cells must be 0)
// ---------------------------------------------------------------------------
__global__ void zero_kernel() {
    const size_t N4 = (size_t)NIMG * HP * WP * 128 * 2 / 16;
    uint4 z = make_uint4(0, 0, 0, 0);
    for (size_t i = blockIdx.x * blockDim.x + threadIdx.x; i < 2 * N4;
         i += (size_t)gridDim.x * blockDim.x) {
        if (i < N4) ((uint4*)g_xh)[i] = z;
        else        ((uint4*)g_xl)[i - N4] = z;
    }
}

// ---------------------------------------------------------------------------
// weights -> [k][co][ci] bf16 hi/lo  +  BN scale/shift
// ---------------------------------------------------------------------------
__global__ void prep_w_kernel(const float* __restrict__ cw,
                              const float* __restrict__ gamma,
                              const float* __restrict__ beta,
                              const float* __restrict__ mean,
                              const float* __restrict__ var) {
    int i = blockIdx.x * blockDim.x + threadIdx.x;
    if (i < 128) {
        float s = gamma[i] * rsqrtf(var[i] + 1e-5f);
        g_bns[i] = s;
        g_bnb[i] = beta[i] - mean[i] * s;
    }
    if (i < 9 * 128 * 128) {
        int ci = i & 127, co = (i >> 7) & 127, k = i >> 14;
        float w = cw[(co * 128 + ci) * 9 + k];
        __nv_bfloat16 hi = __float2bfloat16(w);
        __nv_bfloat16 lo = __float2bfloat16(w - __bfloat162float(hi));
        g_wh[(k * 128 + co) * 128 + ci] = hi;
        g_wl[(k * 128 + co) * 128 + ci] = lo;
    }
}

// ---------------------------------------------------------------------------
// x (NCHW) -> BN+ReLU -> bf16 hi/lo split -> channel-last padded arrays
// ---------------------------------------------------------------------------
__global__ void __launch_bounds__(256) prep_x_kernel(const float* __restrict__ x) {
    __shared__ uint32_t sm[128][65];
    const int h = blockIdx.x, n = blockIdx.y, tid = threadIdx.x;
    for (int half = 0; half < 2; half++) {
        const int w0 = half * 64;
        for (int i = tid; i < 2048; i += 256) {
            int ci = i >> 4, w4 = i & 15;
            const float4 v = *(const float4*)(x + (((size_t)(n * 128 + ci)) * 64 + h) * 128 + w0 + w4 * 4);
            float s = g_bns[ci], b = g_bnb[ci];
            float vs[4] = {v.x, v.y, v.z, v.w};
#pragma unroll
            for (int j = 0; j < 4; j++) {
                float r = fmaxf(fmaf(vs[j], s, b), 0.f);
                __nv_bfloat16 hi = __float2bfloat16(r);
                __nv_bfloat16 lo = __float2bfloat16(r - __bfloat162float(hi));
                sm[ci][w4 * 4 + j] = (uint32_t)__bfloat16_as_ushort(hi) |
                                     ((uint32_t)__bfloat16_as_ushort(lo) << 16);
            }
        }
        __syncthreads();
        {
            const int wl = tid >> 2, ci0 = (tid & 3) * 32;
            uint32_t hb[16], lb[16];
#pragma unroll
            for (int k = 0; k < 16; k++) {
                uint32_t p0 = sm[ci0 + 2 * k][wl];
                uint32_t p1 = sm[ci0 + 2 * k + 1][wl];
                hb[k] = (p0 & 0xffffu) | (p1 << 16);
                lb[k] = (p0 >> 16) | (p1 & 0xffff0000u);
            }
            const size_t base = (((size_t)n * HP + (h + 1)) * WP + (w0 + wl + 1)) * 128 + ci0;
            uint4* dh = (uint4*)(g_xh + base);
            uint4* dl = (uint4*)(g_xl + base);
#pragma unroll
            for (int q = 0; q < 4; q++) {
                dh[q] = ((uint4*)hb)[q];
                dl[q] = ((uint4*)lb)[q];
            }
        }
        __syncthreads();
    }
}

// ---------------------------------------------------------------------------
// conv via warp-level mma.sync (HMMA bf16, 3-split) + fused L2-normalize.
// Block = one (n, h) output row: 8 warps x 16 w = 128 px, all 128 couts.
// Loop (split x ky x ci-chunk of 32): stage A [130 w][32 ci] + B [3kx][128 co][32 ci]
// in smem (rows padded to 40 halves: 80B stride -> conflict-free ldmatrix),
// compute 3 kx x 2 k16-steps x 16 n-tiles of m16n8k16 per warp.
// Epilogue: per-pixel sum-of-squares via quad shfl, rsqrt, normalized store.
// ---------------------------------------------------------------------------
__global__ void __launch_bounds__(256, 1) conv_mma_kernel() {
    __shared__ __align__(16) __nv_bfloat16 As[130 * 40];
    __shared__ __align__(16) __nv_bfloat16 Bs[3][128 * 40];

    const int h = blockIdx.x;
    const int n = blockIdx.y;
    const int tid = threadIdx.x;
    const int wid = tid >> 5, lane = tid & 31;
    const int g = lane >> 2, tig = lane & 3;

    // ldmatrix per-lane address components
    const int arow  = lane & 15;            // A: row within 16-row tile
    const int acolh = (lane >> 4) * 8;      // A: col-half offset (0 or 8)
    const int brow  = (lane & 7) + ((lane >> 4) << 3);  // B: n-row within 16
    const int bcolh = ((lane >> 3) & 1) * 8;            // B: k-half offset

    const uint32_t As_base = smem_to_u32(As);
    const uint32_t Bs_base = smem_to_u32(Bs);

    float4 acc[16];
#pragma unroll
    for (int i = 0; i < 16; i++) acc[i] = make_float4(0.f, 0.f, 0.f, 0.f);

    for (int split = 0; split < 3; split++) {
        const __nv_bfloat16* asrc = (split == 2) ? g_xl : g_xh;
        const __nv_bfloat16* bsrc = (split == 1) ? g_wl : g_wh;
        for (int ky = 0; ky < 3; ky++) {
            const size_t xrow = ((size_t)n * HP + (h + ky)) * WP;
            for (int cc = 0; cc < 4; cc++) {
                const int ci0 = cc * 32;
                __syncthreads();
                // stage A: 130 w x 32 ci (520 uint4)
                for (int i = tid; i < 520; i += 256) {
                    int w = i >> 2, j = i & 3;
                    uint4 v = *(const uint4*)(asrc + (xrow + w) * 128 + ci0 + j * 8);
                    *(uint4*)(As + w * 40 + j * 8) = v;
                }
                // stage B: 3 kx x 128 co x 32 ci (1536 uint4)
                for (int i = tid; i < 1536; i += 256) {
                    int kx = i >> 9;
                    int r  = i & 511;
                    int co = r >> 2, j = r & 3;
                    uint4 v = *(const uint4*)(bsrc + ((size_t)((ky * 3 + kx) * 128 + co)) * 128 + ci0 + j * 8);
                    *(uint4*)(&Bs[kx][co * 40 + j * 8]) = v;
                }
                __syncthreads();
                // compute
#pragma unroll
                for (int kx = 0; kx < 3; kx++) {
#pragma unroll
                    for (int ks = 0; ks < 2; ks++) {
                        uint32_t a[4];
                        uint32_t aaddr = As_base +
                            (uint32_t)(((wid * 16 + kx + arow) * 40 + ks * 16 + acolh) * 2);
                        ldmatrix_x4(a, aaddr);
#pragma unroll
                        for (int nt2 = 0; nt2 < 8; nt2++) {
                            uint32_t b[4];
                            uint32_t baddr = Bs_base + (uint32_t)(kx * (128 * 40 * 2)) +
                                (uint32_t)(((nt2 * 16 + brow) * 40 + ks * 16 + bcolh) * 2);
                            ldmatrix_x4(b, baddr);
                            mma_bf16(acc[nt2 * 2],     a, b[0], b[1]);
                            mma_bf16(acc[nt2 * 2 + 1], a, b[2], b[3]);
                        }
                    }
                }
            }
        }
    }

    // ---- fused L2 normalization (register-resident, quad shfl reduce) ----
    float s0 = 0.f, s1 = 0.f;
#pragma unroll
    for (int nt = 0; nt < 16; nt++) {
        s0 += acc[nt].x * acc[nt].x + acc[nt].y * acc[nt].y;
        s1 += acc[nt].z * acc[nt].z + acc[nt].w * acc[nt].w;
    }
    s0 += __shfl_xor_sync(0xffffffffu, s0, 1);
    s0 += __shfl_xor_sync(0xffffffffu, s0, 2);
    s1 += __shfl_xor_sync(0xffffffffu, s1, 1);
    s1 += __shfl_xor_sync(0xffffffffu, s1, 2);
    const float inv0 = rsqrtf(s0);
    const float inv1 = rsqrtf(s1);

    const int w0 = wid * 16 + g;
    float* d0 = g_feat + ((size_t)(n * HH + h) * WW + w0) * 128;
    float* d1 = d0 + (size_t)8 * 128;
#pragma unroll
    for (int nt = 0; nt < 16; nt++) {
        *(float2*)(d0 + nt * 8 + tig * 2) = make_float2(acc[nt].x * inv0, acc[nt].y * inv0);
        *(float2*)(d1 + nt * 8 + tig * 2) = make_float2(acc[nt].z * inv1, acc[nt].w * inv1);
    }
}

// ---------------------------------------------------------------------------
// 9x9 dilated (x2) correlation (unchanged R2 design)
// ---------------------------------------------------------------------------
__device__ __forceinline__ int cswz(int col, int c2) {
    int k = col >> 3;
    int g = ((k << 1) | (k & 1)) & 7;
    return (col * 2 + c2) ^ g;
}
__device__ __forceinline__ float dot8(const float4 a0, const float4 a1,
                                      const float4 b0, const float4 b1, float s) {
    s = fmaf(a0.x, b0.x, s); s = fmaf(a0.y, b0.y, s);
    s = fmaf(a0.z, b0.z, s); s = fmaf(a0.w, b0.w, s);
    s = fmaf(a1.x, b1.x, s); s = fmaf(a1.y, b1.y, s);
    s = fmaf(a1.z, b1.z, s); s = fmaf(a1.w, b1.w, s);
    return s;
}

__global__ void __launch_bounds__(256, 2) corr_kernel(float* __restrict__ out) {
    __shared__ __align__(16) float4 f2s[8][288];

    const int warp = threadIdx.x >> 5;
    const int lane = threadIdx.x & 31;
    int task = blockIdx.x * 8 + warp;
    int py  = task % 9;
    int rem = task / 9;
    int h   = rem & 63;
    int pb  = rem >> 6;
    int pair = pb % 3, b = pb / 3;
    int n1 = b * 4 + pair, n2 = n1 + 1;
    int row = h + 2 * py - 8;

    const int base = ((lane >> 1) << 3) | (lane & 1);
    float* ob = out + (size_t)(b * 243 + pair * 81 + py * 9) * (HH * WW) + h * WW;

    if (row < 0 || row >= HH) {
#pragma unroll
        for (int px = 0; px < 9; px++)
#pragma unroll
            for (int j = 0; j < 4; j++)
                ob[(size_t)px * (HH * WW) + base + 2 * j] = 0.f;
        return;
    }

    float acc[36];
#pragma unroll
    for (int i = 0; i < 36; i++) acc[i] = 0.f;

    const float4* f1p = (const float4*)g_feat + (size_t)(n1 * HH + h) * WW * 32;
    const float4* f2p = (const float4*)g_feat + (size_t)(n2 * HH + row) * WW * 32;

    for (int ch = 0; ch < 16; ch++) {
        __syncwarp();
#pragma unroll
        for (int m = 0; m < 9; m++) {
            int i = lane + 32 * m;
            int col = i >> 1, c2 = i & 1;
            int gw = col - 8;
            float4 v = make_float4(0.f, 0.f, 0.f, 0.f);
            if (gw >= 0 && gw < WW) v = f2p[gw * 32 + ch * 2 + c2];
            f2s[warp][cswz(col, c2)] = v;
        }
        __syncwarp();

        float4 A[4][2];
#pragma unroll
        for (int j = 0; j < 4; j++) {
            A[j][0] = f1p[(base + 2 * j) * 32 + ch * 2 + 0];
            A[j][1] = f1p[(base + 2 * j) * 32 + ch * 2 + 1];
        }
#pragma unroll
        for (int t = 0; t < 12; t++) {
            int col = base + 2 * t;
            float4 B0 = f2s[warp][cswz(col, 0)];
            float4 B1 = f2s[warp][cswz(col, 1)];
#pragma unroll
            for (int j = 0; j < 4; j++) {
                int px = t - j;
                if (px >= 0 && px < 9)
                    acc[px * 4 + j] = dot8(A[j][0], A[j][1], B0, B1, acc[px * 4 + j]);
            }
        }
    }
#pragma unroll
    for (int px = 0; px < 9; px++)
#pragma unroll
        for (int j = 0; j < 4; j++)
            ob[(size_t)px * (HH * WW) + base + 2 * j] = acc[px * 4 + j];
}

// ---------------------------------------------------------------------------
extern "C" void kernel_launch(void* const* d_in, const int* in_sizes, int n_in,
                              void* d_out, int out_size) {
    const float* x     = (const float*)d_in[0];
    const float* gamma = (const float*)d_in[1];
    const float* beta  = (const float*)d_in[2];
    const float* mean  = (const float*)d_in[3];
    const float* var   = (const float*)d_in[4];
    const float* cw    = (const float*)d_in[5];
    float* out = (float*)d_out;

    zero_kernel<<<2048, 256>>>();
    prep_w_kernel<<<(9 * 128 * 128 + 255) / 256, 256>>>(cw, gamma, beta, mean, var);
    prep_x_kernel<<<dim3(HH, NIMG), 256>>>(x);
    conv_mma_kernel<<<dim3(HH, NIMG), 256>>>();
    corr_kernel<<<864, 256>>>(out);
}

// round 16
// speedup vs baseline: 2.0715x; 1.5082x over previous
#include <cuda_runtime.h>
#include <cuda_bf16.h>
#include <cstdint>

#define HH   64
#define WW   128
#define NIMG 16
#define HP   66
#define WP   130

// ---------------- scratch (static device arrays; allocation-free) ----------
__device__ __nv_bfloat16 g_xh[(size_t)NIMG * HP * WP * 128];   // BN+ReLU input hi, channel-last, padded
__device__ __nv_bfloat16 g_xl[(size_t)NIMG * HP * WP * 128];   // lo part
__device__ __nv_bfloat16 g_wh[9 * 128 * 128];                  // weights hi  [k][co][ci]
__device__ __nv_bfloat16 g_wl[9 * 128 * 128];                  // weights lo
__device__ float g_feat[(size_t)NIMG * HH * WW * 128];         // normalized features, channel-last
__device__ float g_bns[128];
__device__ float g_bnb[128];

__device__ __forceinline__ uint32_t smem_to_u32(const void* p) {
    uint32_t a;
    asm("{ .reg .u64 t; cvta.to.shared.u64 t, %1; cvt.u32.u64 %0, t; }" : "=r"(a) : "l"(p));
    return a;
}
__device__ __forceinline__ void ldmatrix_x4(uint32_t* r, uint32_t addr) {
    asm volatile("ldmatrix.sync.aligned.m8n8.x4.shared.b16 {%0,%1,%2,%3}, [%4];"
                 : "=r"(r[0]), "=r"(r[1]), "=r"(r[2]), "=r"(r[3]) : "r"(addr));
}
__device__ __forceinline__ void mma_bf16(float4& d, const uint32_t* a, uint32_t b0, uint32_t b1) {
    asm volatile("mma.sync.aligned.m16n8k16.row.col.f32.bf16.bf16.f32 "
                 "{%0,%1,%2,%3}, {%4,%5,%6,%7}, {%8,%9}, {%0,%1,%2,%3};"
                 : "+f"(d.x), "+f"(d.y), "+f"(d.z), "+f"(d.w)
                 : "r"(a[0]), "r"(a[1]), "r"(a[2]), "r"(a[3]), "r"(b0), "r"(b1));
}
__device__ __forceinline__ void cp16(uint32_t dst, const void* src) {
    asm volatile("cp.async.cg.shared.global [%0], [%1], 16;" :: "r"(dst), "l"(src));
}
__device__ __forceinline__ void cp_commit() {
    asm volatile("cp.async.commit_group;" ::: "memory");
}
__device__ __forceinline__ void cp_wait0() {
    asm volatile("cp.async.wait_group 0;" ::: "memory");
}

// ---------------------------------------------------------------------------
// zero-fill padded input arrays (padding cells must be 0)
// ---------------------------------------------------------------------------
__global__ void zero_kernel() {
    const size_t N4 = (size_t)NIMG * HP * WP * 128 * 2 / 16;
    uint4 z = make_uint4(0, 0, 0, 0);
    for (size_t i = blockIdx.x * blockDim.x + threadIdx.x; i < 2 * N4;
         i += (size_t)gridDim.x * blockDim.x) {
        if (i < N4) ((uint4*)g_xh)[i] = z;
        else        ((uint4*)g_xl)[i - N4] = z;
    }
}

// ---------------------------------------------------------------------------
// weights -> [k][co][ci] bf16 hi/lo  +  BN scale/shift
// ---------------------------------------------------------------------------
__global__ void prep_w_kernel(const float* __restrict__ cw,
                              const float* __restrict__ gamma,
                              const float* __restrict__ beta,
                              const float* __restrict__ mean,
                              const float* __restrict__ var) {
    int i = blockIdx.x * blockDim.x + threadIdx.x;
    if (i < 128) {
        float s = gamma[i] * rsqrtf(var[i] + 1e-5f);
        g_bns[i] = s;
        g_bnb[i] = beta[i] - mean[i] * s;
    }
    if (i < 9 * 128 * 128) {
        int ci = i & 127, co = (i >> 7) & 127, k = i >> 14;
        float w = cw[(co * 128 + ci) * 9 + k];
        __nv_bfloat16 hi = __float2bfloat16(w);
        __nv_bfloat16 lo = __float2bfloat16(w - __bfloat162float(hi));
        g_wh[(k * 128 + co) * 128 + ci] = hi;
        g_wl[(k * 128 + co) * 128 + ci] = lo;
    }
}

// ---------------------------------------------------------------------------
// x (NCHW) -> BN+ReLU -> bf16 hi/lo split -> channel-last padded arrays
// ---------------------------------------------------------------------------
__global__ void __launch_bounds__(256) prep_x_kernel(const float* __restrict__ x) {
    __shared__ uint32_t sm[128][65];
    const int h = blockIdx.x, n = blockIdx.y, tid = threadIdx.x;
    for (int half = 0; half < 2; half++) {
        const int w0 = half * 64;
        for (int i = tid; i < 2048; i += 256) {
            int ci = i >> 4, w4 = i & 15;
            const float4 v = *(const float4*)(x + (((size_t)(n * 128 + ci)) * 64 + h) * 128 + w0 + w4 * 4);
            float s = g_bns[ci], b = g_bnb[ci];
            float vs[4] = {v.x, v.y, v.z, v.w};
#pragma unroll
            for (int j = 0; j < 4; j++) {
                float r = fmaxf(fmaf(vs[j], s, b), 0.f);
                __nv_bfloat16 hi = __float2bfloat16(r);
                __nv_bfloat16 lo = __float2bfloat16(r - __bfloat162float(hi));
                sm[ci][w4 * 4 + j] = (uint32_t)__bfloat16_as_ushort(hi) |
                                     ((uint32_t)__bfloat16_as_ushort(lo) << 16);
            }
        }
        __syncthreads();
        {
            const int wl = tid >> 2, ci0 = (tid & 3) * 32;
            uint32_t hb[16], lb[16];
#pragma unroll
            for (int k = 0; k < 16; k++) {
                uint32_t p0 = sm[ci0 + 2 * k][wl];
                uint32_t p1 = sm[ci0 + 2 * k + 1][wl];
                hb[k] = (p0 & 0xffffu) | (p1 << 16);
                lb[k] = (p0 >> 16) | (p1 & 0xffff0000u);
            }
            const size_t base = (((size_t)n * HP + (h + 1)) * WP + (w0 + wl + 1)) * 128 + ci0;
            uint4* dh = (uint4*)(g_xh + base);
            uint4* dl = (uint4*)(g_xl + base);
#pragma unroll
            for (int q = 0; q < 4; q++) {
                dh[q] = ((uint4*)hb)[q];
                dl[q] = ((uint4*)lb)[q];
            }
        }
        __syncthreads();
    }
}

// ---------------------------------------------------------------------------
// conv via warp-level mma.sync (HMMA bf16, 3-split) + fused L2-normalize.
// Block = one (n, h) row: 8 warps x 16 w, all 128 couts.
// 36 chunks (split x ky x ci32), cp.async double-buffered: stage chunk c+1
// overlaps compute of chunk c (wait0 -> bar -> issue c+1 -> compute c).
// Smem per stage: A [130 w][32 ci] + B [3kx][128 co][32 ci], rows padded to
// 40 halves (80B stride -> conflict-free ldmatrix).
// ---------------------------------------------------------------------------
#define A_BYTES   (130 * 40 * 2)            // 10400
#define B_BYTES   (3 * 128 * 40 * 2)        // 30720
#define KX_BYTES  (128 * 40 * 2)            // 10240
#define STAGE_BYTES (A_BYTES + B_BYTES)     // 41120
#define CONV_SMEM (2 * STAGE_BYTES)         // 82240

__device__ __forceinline__ void stage_chunk(int c, uint32_t sbase, int n, int h, int tid) {
    const int split = c / 12;
    const int rem   = c % 12;
    const int ky    = rem >> 2;
    const int ci0   = (rem & 3) * 32;
    const __nv_bfloat16* asrc = (split == 2) ? g_xl : g_xh;
    const __nv_bfloat16* bsrc = (split == 1) ? g_wl : g_wh;
    const size_t xrow = ((size_t)n * HP + (h + ky)) * WP;
    // A: 130 w x 32 ci  (520 x 16B)
    for (int i = tid; i < 520; i += 256) {
        int w = i >> 2, j = i & 3;
        cp16(sbase + (uint32_t)((w * 40 + j * 8) * 2),
             asrc + (xrow + w) * 128 + ci0 + j * 8);
    }
    // B: 3 kx x 128 co x 32 ci  (1536 x 16B)
    for (int i = tid; i < 1536; i += 256) {
        int kx = i >> 9;
        int r  = i & 511;
        int co = r >> 2, j = r & 3;
        cp16(sbase + (uint32_t)(A_BYTES + kx * KX_BYTES + (co * 40 + j * 8) * 2),
             bsrc + ((size_t)((ky * 3 + kx) * 128 + co)) * 128 + ci0 + j * 8);
    }
    cp_commit();
}

__global__ void __launch_bounds__(256, 1) conv_mma_kernel() {
    extern __shared__ __align__(16) char dsm[];
    const uint32_t sb = smem_to_u32(dsm);

    const int h = blockIdx.x;
    const int n = blockIdx.y;
    const int tid = threadIdx.x;
    const int wid = tid >> 5, lane = tid & 31;
    const int g = lane >> 2, tig = lane & 3;

    const int arow  = lane & 15;
    const int acolh = (lane >> 4) * 8;
    const int brow  = (lane & 7) + ((lane >> 4) << 3);
    const int bcolh = ((lane >> 3) & 1) * 8;

    float4 acc[16];
#pragma unroll
    for (int i = 0; i < 16; i++) acc[i] = make_float4(0.f, 0.f, 0.f, 0.f);

    stage_chunk(0, sb, n, h, tid);

    for (int c = 0; c < 36; c++) {
        const uint32_t cur = sb + (uint32_t)((c & 1) * STAGE_BYTES);
        cp_wait0();
        __syncthreads();
        if (c + 1 < 36)
            stage_chunk(c + 1, sb + (uint32_t)(((c + 1) & 1) * STAGE_BYTES), n, h, tid);
        // compute chunk c from buffer `cur`
#pragma unroll
        for (int kx = 0; kx < 3; kx++) {
#pragma unroll
            for (int ks = 0; ks < 2; ks++) {
                uint32_t a[4];
                uint32_t aaddr = cur +
                    (uint32_t)(((wid * 16 + kx + arow) * 40 + ks * 16 + acolh) * 2);
                ldmatrix_x4(a, aaddr);
#pragma unroll
                for (int nt2 = 0; nt2 < 8; nt2++) {
                    uint32_t b[4];
                    uint32_t baddr = cur + (uint32_t)(A_BYTES + kx * KX_BYTES) +
                        (uint32_t)(((nt2 * 16 + brow) * 40 + ks * 16 + bcolh) * 2);
                    ldmatrix_x4(b, baddr);
                    mma_bf16(acc[nt2 * 2],     a, b[0], b[1]);
                    mma_bf16(acc[nt2 * 2 + 1], a, b[2], b[3]);
                }
            }
        }
    }

    // ---- fused L2 normalization (register-resident, quad shfl reduce) ----
    float s0 = 0.f, s1 = 0.f;
#pragma unroll
    for (int nt = 0; nt < 16; nt++) {
        s0 += acc[nt].x * acc[nt].x + acc[nt].y * acc[nt].y;
        s1 += acc[nt].z * acc[nt].z + acc[nt].w * acc[nt].w;
    }
    s0 += __shfl_xor_sync(0xffffffffu, s0, 1);
    s0 += __shfl_xor_sync(0xffffffffu, s0, 2);
    s1 += __shfl_xor_sync(0xffffffffu, s1, 1);
    s1 += __shfl_xor_sync(0xffffffffu, s1, 2);
    const float inv0 = rsqrtf(s0);
    const float inv1 = rsqrtf(s1);

    const int w0 = wid * 16 + g;
    float* d0 = g_feat + ((size_t)(n * HH + h) * WW + w0) * 128;
    float* d1 = d0 + (size_t)8 * 128;
#pragma unroll
    for (int nt = 0; nt < 16; nt++) {
        *(float2*)(d0 + nt * 8 + tig * 2) = make_float2(acc[nt].x * inv0, acc[nt].y * inv0);
        *(float2*)(d1 + nt * 8 + tig * 2) = make_float2(acc[nt].z * inv1, acc[nt].w * inv1);
    }
}

// ---------------------------------------------------------------------------
// 9x9 dilated (x2) correlation (unchanged)
// ---------------------------------------------------------------------------
__device__ __forceinline__ int cswz(int col, int c2) {
    int k = col >> 3;
    int g = ((k << 1) | (k & 1)) & 7;
    return (col * 2 + c2) ^ g;
}
__device__ __forceinline__ float dot8(const float4 a0, const float4 a1,
                                      const float4 b0, const float4 b1, float s) {
    s = fmaf(a0.x, b0.x, s); s = fmaf(a0.y, b0.y, s);
    s = fmaf(a0.z, b0.z, s); s = fmaf(a0.w, b0.w, s);
    s = fmaf(a1.x, b1.x, s); s = fmaf(a1.y, b1.y, s);
    s = fmaf(a1.z, b1.z, s); s = fmaf(a1.w, b1.w, s);
    return s;
}

__global__ void __launch_bounds__(256, 2) corr_kernel(float* __restrict__ out) {
    __shared__ __align__(16) float4 f2s[8][288];

    const int warp = threadIdx.x >> 5;
    const int lane = threadIdx.x & 31;
    int task = blockIdx.x * 8 + warp;
    int py  = task % 9;
    int rem = task / 9;
    int h   = rem & 63;
    int pb  = rem >> 6;
    int pair = pb % 3, b = pb / 3;
    int n1 = b * 4 + pair, n2 = n1 + 1;
    int row = h + 2 * py - 8;

    const int base = ((lane >> 1) << 3) | (lane & 1);
    float* ob = out + (size_t)(b * 243 + pair * 81 + py * 9) * (HH * WW) + h * WW;

    if (row < 0 || row >= HH) {
#pragma unroll
        for (int px = 0; px < 9; px++)
#pragma unroll
            for (int j = 0; j < 4; j++)
                ob[(size_t)px * (HH * WW) + base + 2 * j] = 0.f;
        return;
    }

    float acc[36];
#pragma unroll
    for (int i = 0; i < 36; i++) acc[i] = 0.f;

    const float4* f1p = (const float4*)g_feat + (size_t)(n1 * HH + h) * WW * 32;
    const float4* f2p = (const float4*)g_feat + (size_t)(n2 * HH + row) * WW * 32;

    for (int ch = 0; ch < 16; ch++) {
        __syncwarp();
#pragma unroll
        for (int m = 0; m < 9; m++) {
            int i = lane + 32 * m;
            int col = i >> 1, c2 = i & 1;
            int gw = col - 8;
            float4 v = make_float4(0.f, 0.f, 0.f, 0.f);
            if (gw >= 0 && gw < WW) v = f2p[gw * 32 + ch * 2 + c2];
            f2s[warp][cswz(col, c2)] = v;
        }
        __syncwarp();

        float4 A[4][2];
#pragma unroll
        for (int j = 0; j < 4; j++) {
            A[j][0] = f1p[(base + 2 * j) * 32 + ch * 2 + 0];
            A[j][1] = f1p[(base + 2 * j) * 32 + ch * 2 + 1];
        }
#pragma unroll
        for (int t = 0; t < 12; t++) {
            int col = base + 2 * t;
            float4 B0 = f2s[warp][cswz(col, 0)];
            float4 B1 = f2s[warp][cswz(col, 1)];
#pragma unroll
            for (int j = 0; j < 4; j++) {
                int px = t - j;
                if (px >= 0 && px < 9)
                    acc[px * 4 + j] = dot8(A[j][0], A[j][1], B0, B1, acc[px * 4 + j]);
            }
        }
    }
#pragma unroll
    for (int px = 0; px < 9; px++)
#pragma unroll
        for (int j = 0; j < 4; j++)
            ob[(size_t)px * (HH * WW) + base + 2 * j] = acc[px * 4 + j];
}

// ---------------------------------------------------------------------------
extern "C" void kernel_launch(void* const* d_in, const int* in_sizes, int n_in,
                              void* d_out, int out_size) {
    const float* x     = (const float*)d_in[0];
    const float* gamma = (const float*)d_in[1];
    const float* beta  = (const float*)d_in[2];
    const float* mean  = (const float*)d_in[3];
    const float* var   = (const float*)d_in[4];
    const float* cw    = (const float*)d_in[5];
    float* out = (float*)d_out;

    cudaFuncSetAttribute(conv_mma_kernel, cudaFuncAttributeMaxDynamicSharedMemorySize, CONV_SMEM);

    zero_kernel<<<2048, 256>>>();
    prep_w_kernel<<<(9 * 128 * 128 + 255) / 256, 256>>>(cw, gamma, beta, mean, var);
    prep_x_kernel<<<dim3(HH, NIMG), 256>>>(x);
    conv_mma_kernel<<<dim3(HH, NIMG), 256, CONV_SMEM>>>();
    corr_kernel<<<864, 256>>>(out);
}

// round 17
// speedup vs baseline: 2.2814x; 1.1013x over previous
#include <cuda_runtime.h>
#include <cuda_bf16.h>
#include <cstdint>

#define HH   64
#define WW   128
#define NIMG 16
#define HP   66
#define WP   130

// ---------------- scratch (static device arrays; allocation-free) ----------
__device__ __nv_bfloat16 g_xh[(size_t)NIMG * HP * WP * 128];
__device__ __nv_bfloat16 g_xl[(size_t)NIMG * HP * WP * 128];
__device__ __nv_bfloat16 g_wh[9 * 128 * 128];
__device__ __nv_bfloat16 g_wl[9 * 128 * 128];
__device__ float g_feat[(size_t)NIMG * HH * WW * 128];
__device__ float g_bns[128];
__device__ float g_bnb[128];

__device__ __forceinline__ uint32_t smem_to_u32(const void* p) {
    uint32_t a;
    asm("{ .reg .u64 t; cvta.to.shared.u64 t, %1; cvt.u32.u64 %0, t; }" : "=r"(a) : "l"(p));
    return a;
}
__device__ __forceinline__ void ldmatrix_x4(uint32_t* r, uint32_t addr) {
    asm volatile("ldmatrix.sync.aligned.m8n8.x4.shared.b16 {%0,%1,%2,%3}, [%4];"
                 : "=r"(r[0]), "=r"(r[1]), "=r"(r[2]), "=r"(r[3]) : "r"(addr));
}
__device__ __forceinline__ void mma_bf16(float4& d, const uint32_t* a, uint32_t b0, uint32_t b1) {
    asm volatile("mma.sync.aligned.m16n8k16.row.col.f32.bf16.bf16.f32 "
                 "{%0,%1,%2,%3}, {%4,%5,%6,%7}, {%8,%9}, {%0,%1,%2,%3};"
                 : "+f"(d.x), "+f"(d.y), "+f"(d.z), "+f"(d.w)
                 : "r"(a[0]), "r"(a[1]), "r"(a[2]), "r"(a[3]), "r"(b0), "r"(b1));
}
__device__ __forceinline__ void cp16(uint32_t dst, const void* src) {
    asm volatile("cp.async.cg.shared.global [%0], [%1], 16;" :: "r"(dst), "l"(src));
}
__device__ __forceinline__ void cp_commit() {
    asm volatile("cp.async.commit_group;" ::: "memory");
}
__device__ __forceinline__ void cp_wait0() {
    asm volatile("cp.async.wait_group 0;" ::: "memory");
}

// ---------------------------------------------------------------------------
__global__ void zero_kernel() {
    const size_t N4 = (size_t)NIMG * HP * WP * 128 * 2 / 16;
    uint4 z = make_uint4(0, 0, 0, 0);
    for (size_t i = blockIdx.x * blockDim.x + threadIdx.x; i < 2 * N4;
         i += (size_t)gridDim.x * blockDim.x) {
        if (i < N4) ((uint4*)g_xh)[i] = z;
        else        ((uint4*)g_xl)[i - N4] = z;
    }
}

// ---------------------------------------------------------------------------
__global__ void prep_w_kernel(const float* __restrict__ cw,
                              const float* __restrict__ gamma,
                              const float* __restrict__ beta,
                              const float* __restrict__ mean,
                              const float* __restrict__ var) {
    int i = blockIdx.x * blockDim.x + threadIdx.x;
    if (i < 128) {
        float s = gamma[i] * rsqrtf(var[i] + 1e-5f);
        g_bns[i] = s;
        g_bnb[i] = beta[i] - mean[i] * s;
    }
    if (i < 9 * 128 * 128) {
        int ci = i & 127, co = (i >> 7) & 127, k = i >> 14;
        float w = cw[(co * 128 + ci) * 9 + k];
        __nv_bfloat16 hi = __float2bfloat16(w);
        __nv_bfloat16 lo = __float2bfloat16(w - __bfloat162float(hi));
        g_wh[(k * 128 + co) * 128 + ci] = hi;
        g_wl[(k * 128 + co) * 128 + ci] = lo;
    }
}

// ---------------------------------------------------------------------------
__global__ void __launch_bounds__(256) prep_x_kernel(const float* __restrict__ x) {
    __shared__ uint32_t sm[128][65];
    const int h = blockIdx.x, n = blockIdx.y, tid = threadIdx.x;
    for (int half = 0; half < 2; half++) {
        const int w0 = half * 64;
        for (int i = tid; i < 2048; i += 256) {
            int ci = i >> 4, w4 = i & 15;
            const float4 v = *(const float4*)(x + (((size_t)(n * 128 + ci)) * 64 + h) * 128 + w0 + w4 * 4);
            float s = g_bns[ci], b = g_bnb[ci];
            float vs[4] = {v.x, v.y, v.z, v.w};
#pragma unroll
            for (int j = 0; j < 4; j++) {
                float r = fmaxf(fmaf(vs[j], s, b), 0.f);
                __nv_bfloat16 hi = __float2bfloat16(r);
                __nv_bfloat16 lo = __float2bfloat16(r - __bfloat162float(hi));
                sm[ci][w4 * 4 + j] = (uint32_t)__bfloat16_as_ushort(hi) |
                                     ((uint32_t)__bfloat16_as_ushort(lo) << 16);
            }
        }
        __syncthreads();
        {
            const int wl = tid >> 2, ci0 = (tid & 3) * 32;
            uint32_t hb[16], lb[16];
#pragma unroll
            for (int k = 0; k < 16; k++) {
                uint32_t p0 = sm[ci0 + 2 * k][wl];
                uint32_t p1 = sm[ci0 + 2 * k + 1][wl];
                hb[k] = (p0 & 0xffffu) | (p1 << 16);
                lb[k] = (p0 >> 16) | (p1 & 0xffff0000u);
            }
            const size_t base = (((size_t)n * HP + (h + 1)) * WP + (w0 + wl + 1)) * 128 + ci0;
            uint4* dh = (uint4*)(g_xh + base);
            uint4* dl = (uint4*)(g_xl + base);
#pragma unroll
            for (int q = 0; q < 4; q++) {
                dh[q] = ((uint4*)hb)[q];
                dl[q] = ((uint4*)lb)[q];
            }
        }
        __syncthreads();
    }
}

// ---------------------------------------------------------------------------
// conv v3: HMMA bf16 3-split, warp tile 32w x 64co, 2 output rows per block,
// B fragments persisted in registers across both rows (weights identical),
// cp.async double-buffered. 8 warps = 4 w-groups x 2 co-groups.
// Stage: A[2 rows][130][40] + B[3 kx][128 co][40] (rows 40-half-padded).
// ---------------------------------------------------------------------------
#define A1_BYTES  (130 * 40 * 2)            // 10400 per row
#define B_OFF     (2 * A1_BYTES)            // 20800
#define KX_BYTES  (128 * 40 * 2)            // 10240
#define STAGE_BYTES (B_OFF + 3 * KX_BYTES)  // 51520
#define CONV_SMEM (2 * STAGE_BYTES)         // 103040

__device__ __forceinline__ void stage_chunk(int c, uint32_t sbase, int n, int h0, int tid) {
    const int split = c / 12;
    const int rem   = c % 12;
    const int ky    = rem >> 2;
    const int ci0   = (rem & 3) * 32;
    const __nv_bfloat16* asrc = (split == 2) ? g_xl : g_xh;
    const __nv_bfloat16* bsrc = (split == 1) ? g_wl : g_wh;
    // A: 2 rows x 130 w x 32 ci (1040 x 16B)
    for (int i = tid; i < 1040; i += 256) {
        int hh = i >= 520;
        int r  = i - hh * 520;
        int w = r >> 2, j = r & 3;
        cp16(sbase + (uint32_t)(hh * A1_BYTES + (w * 40 + j * 8) * 2),
             asrc + (((size_t)n * HP + (h0 + hh + ky)) * WP + w) * 128 + ci0 + j * 8);
    }
    // B: 3 kx x 128 co x 32 ci (1536 x 16B)
    for (int i = tid; i < 1536; i += 256) {
        int kx = i >> 9;
        int r  = i & 511;
        int co = r >> 2, j = r & 3;
        cp16(sbase + (uint32_t)(B_OFF + kx * KX_BYTES + (co * 40 + j * 8) * 2),
             bsrc + ((size_t)((ky * 3 + kx) * 128 + co)) * 128 + ci0 + j * 8);
    }
    cp_commit();
}

__global__ void __launch_bounds__(256, 1) conv_mma_kernel() {
    extern __shared__ __align__(16) char dsm[];
    __shared__ float psum[2][2][128];   // [co-group][hh][w]
    const uint32_t sb = smem_to_u32(dsm);

    const int h0 = blockIdx.x * 2;
    const int n  = blockIdx.y;
    const int tid = threadIdx.x;
    const int wid = tid >> 5, lane = tid & 31;
    const int g = lane >> 2, tig = lane & 3;
    const int wg  = wid & 3;          // w-group: w0 = wg*32
    const int cog = wid >> 2;         // co-group: co0 = cog*64
    const int w0  = wg * 32;
    const int co0 = cog * 64;

    const int arow  = lane & 15;
    const int acolh = (lane >> 4) * 8;
    const int brow  = (lane & 7) + ((lane >> 4) << 3);
    const int bcolh = ((lane >> 3) & 1) * 8;

    float4 acc[2][2][8];   // [hh][m-tile][t*2+p]
#pragma unroll
    for (int a = 0; a < 2; a++)
#pragma unroll
        for (int m = 0; m < 2; m++)
#pragma unroll
            for (int i = 0; i < 8; i++) acc[a][m][i] = make_float4(0.f, 0.f, 0.f, 0.f);

    stage_chunk(0, sb, n, h0, tid);

    for (int c = 0; c < 36; c++) {
        const uint32_t cur = sb + (uint32_t)((c & 1) * STAGE_BYTES);
        cp_wait0();
        __syncthreads();
        if (c + 1 < 36)
            stage_chunk(c + 1, sb + (uint32_t)(((c + 1) & 1) * STAGE_BYTES), n, h0, tid);

#pragma unroll
        for (int kx = 0; kx < 3; kx++) {
            // load B fragments once per kx, reuse for both h rows
            uint32_t breg[4][2][4];   // [n16-tile][ks][4]
#pragma unroll
            for (int t = 0; t < 4; t++)
#pragma unroll
                for (int ks = 0; ks < 2; ks++) {
                    uint32_t baddr = cur + (uint32_t)(B_OFF + kx * KX_BYTES) +
                        (uint32_t)(((co0 + t * 16 + brow) * 40 + ks * 16 + bcolh) * 2);
                    ldmatrix_x4(breg[t][ks], baddr);
                }
#pragma unroll
            for (int hh = 0; hh < 2; hh++) {
#pragma unroll
                for (int ks = 0; ks < 2; ks++) {
                    uint32_t a0[4], a1[4];
                    uint32_t abase = cur + (uint32_t)(hh * A1_BYTES);
                    ldmatrix_x4(a0, abase + (uint32_t)(((w0 + kx + arow) * 40 + ks * 16 + acolh) * 2));
                    ldmatrix_x4(a1, abase + (uint32_t)(((w0 + 16 + kx + arow) * 40 + ks * 16 + acolh) * 2));
#pragma unroll
                    for (int t = 0; t < 4; t++) {
                        mma_bf16(acc[hh][0][t * 2],     a0, breg[t][ks][0], breg[t][ks][1]);
                        mma_bf16(acc[hh][0][t * 2 + 1], a0, breg[t][ks][2], breg[t][ks][3]);
                        mma_bf16(acc[hh][1][t * 2],     a1, breg[t][ks][0], breg[t][ks][1]);
                        mma_bf16(acc[hh][1][t * 2 + 1], a1, breg[t][ks][2], breg[t][ks][3]);
                    }
                }
            }
        }
    }

    // ---- epilogue: cross-co-group L2 norm, then normalized stores ----
#pragma unroll
    for (int hh = 0; hh < 2; hh++)
#pragma unroll
        for (int m = 0; m < 2; m++) {
            float s0 = 0.f, s1 = 0.f;
#pragma unroll
            for (int i = 0; i < 8; i++) {
                s0 += acc[hh][m][i].x * acc[hh][m][i].x + acc[hh][m][i].y * acc[hh][m][i].y;
                s1 += acc[hh][m][i].z * acc[hh][m][i].z + acc[hh][m][i].w * acc[hh][m][i].w;
            }
            s0 += __shfl_xor_sync(0xffffffffu, s0, 1);
            s0 += __shfl_xor_sync(0xffffffffu, s0, 2);
            s1 += __shfl_xor_sync(0xffffffffu, s1, 1);
            s1 += __shfl_xor_sync(0xffffffffu, s1, 2);
            if (tig == 0) {
                psum[cog][hh][w0 + m * 16 + g]     = s0;
                psum[cog][hh][w0 + m * 16 + g + 8] = s1;
            }
        }
    __syncthreads();

#pragma unroll
    for (int hh = 0; hh < 2; hh++)
#pragma unroll
        for (int m = 0; m < 2; m++) {
            const int wa = w0 + m * 16 + g;
            const int wb = wa + 8;
            const float inv0 = rsqrtf(psum[0][hh][wa] + psum[1][hh][wa]);
            const float inv1 = rsqrtf(psum[0][hh][wb] + psum[1][hh][wb]);
            float* da = g_feat + ((size_t)(n * HH + h0 + hh) * WW + wa) * 128 + co0;
            float* db = g_feat + ((size_t)(n * HH + h0 + hh) * WW + wb) * 128 + co0;
#pragma unroll
            for (int i = 0; i < 8; i++) {
                int t = i >> 1, p = i & 1;
                int coff = t * 16 + p * 8 + tig * 2;
                *(float2*)(da + coff) = make_float2(acc[hh][m][i].x * inv0, acc[hh][m][i].y * inv0);
                *(float2*)(db + coff) = make_float2(acc[hh][m][i].z * inv1, acc[hh][m][i].w * inv1);
            }
        }
}

// ---------------------------------------------------------------------------
// 9x9 dilated (x2) correlation (unchanged)
// ---------------------------------------------------------------------------
__device__ __forceinline__ int cswz(int col, int c2) {
    int k = col >> 3;
    int g = ((k << 1) | (k & 1)) & 7;
    return (col * 2 + c2) ^ g;
}
__device__ __forceinline__ float dot8(const float4 a0, const float4 a1,
                                      const float4 b0, const float4 b1, float s) {
    s = fmaf(a0.x, b0.x, s); s = fmaf(a0.y, b0.y, s);
    s = fmaf(a0.z, b0.z, s); s = fmaf(a0.w, b0.w, s);
    s = fmaf(a1.x, b1.x, s); s = fmaf(a1.y, b1.y, s);
    s = fmaf(a1.z, b1.z, s); s = fmaf(a1.w, b1.w, s);
    return s;
}

__global__ void __launch_bounds__(256, 2) corr_kernel(float* __restrict__ out) {
    __shared__ __align__(16) float4 f2s[8][288];

    const int warp = threadIdx.x >> 5;
    const int lane = threadIdx.x & 31;
    int task = blockIdx.x * 8 + warp;
    int py  = task % 9;
    int rem = task / 9;
    int h   = rem & 63;
    int pb  = rem >> 6;
    int pair = pb % 3, b = pb / 3;
    int n1 = b * 4 + pair, n2 = n1 + 1;
    int row = h + 2 * py - 8;

    const int base = ((lane >> 1) << 3) | (lane & 1);
    float* ob = out + (size_t)(b * 243 + pair * 81 + py * 9) * (HH * WW) + h * WW;

    if (row < 0 || row >= HH) {
#pragma unroll
        for (int px = 0; px < 9; px++)
#pragma unroll
            for (int j = 0; j < 4; j++)
                ob[(size_t)px * (HH * WW) + base + 2 * j] = 0.f;
        return;
    }

    float acc[36];
#pragma unroll
    for (int i = 0; i < 36; i++) acc[i] = 0.f;

    const float4* f1p = (const float4*)g_feat + (size_t)(n1 * HH + h) * WW * 32;
    const float4* f2p = (const float4*)g_feat + (size_t)(n2 * HH + row) * WW * 32;

    for (int ch = 0; ch < 16; ch++) {
        __syncwarp();
#pragma unroll
        for (int m = 0; m < 9; m++) {
            int i = lane + 32 * m;
            int col = i >> 1, c2 = i & 1;
            int gw = col - 8;
            float4 v = make_float4(0.f, 0.f, 0.f, 0.f);
            if (gw >= 0 && gw < WW) v = f2p[gw * 32 + ch * 2 + c2];
            f2s[warp][cswz(col, c2)] = v;
        }
        __syncwarp();

        float4 A[4][2];
#pragma unroll
        for (int j = 0; j < 4; j++) {
            A[j][0] = f1p[(base + 2 * j) * 32 + ch * 2 + 0];
            A[j][1] = f1p[(base + 2 * j) * 32 + ch * 2 + 1];
        }
#pragma unroll
        for (int t = 0; t < 12; t++) {
            int col = base + 2 * t;
            float4 B0 = f2s[warp][cswz(col, 0)];
            float4 B1 = f2s[warp][cswz(col, 1)];
#pragma unroll
            for (int j = 0; j < 4; j++) {
                int px = t - j;
                if (px >= 0 && px < 9)
                    acc[px * 4 + j] = dot8(A[j][0], A[j][1], B0, B1, acc[px * 4 + j]);
            }
        }
    }
#pragma unroll
    for (int px = 0; px < 9; px++)
#pragma unroll
        for (int j = 0; j < 4; j++)
            ob[(size_t)px * (HH * WW) + base + 2 * j] = acc[px * 4 + j];
}

// ---------------------------------------------------------------------------
extern "C" void kernel_launch(void* const* d_in, const int* in_sizes, int n_in,
                              void* d_out, int out_size) {
    const float* x     = (const float*)d_in[0];
    const float* gamma = (const float*)d_in[1];
    const float* beta  = (const float*)d_in[2];
    const float* mean  = (const float*)d_in[3];
    const float* var   = (const float*)d_in[4];
    const float* cw    = (const float*)d_in[5];
    float* out = (float*)d_out;

    cudaFuncSetAttribute(conv_mma_kernel, cudaFuncAttributeMaxDynamicSharedMemorySize, CONV_SMEM);

    zero_kernel<<<2048, 256>>>();
    prep_w_kernel<<<(9 * 128 * 128 + 255) / 256, 256>>>(cw, gamma, beta, mean, var);
    prep_x_kernel<<<dim3(HH, NIMG), 256>>>(x);
    conv_mma_kernel<<<dim3(HH / 2, NIMG), 256, CONV_SMEM>>>();
    corr_kernel<<<864, 256>>>(out);
}